// round 8
// baseline (speedup 1.0000x reference)
#include <cuda_runtime.h>
#include <cuda_fp16.h>
#include <math.h>

#define NTOK 4096
#define HID  1024
#define ADIM 64
#define NCAT 8
#define MAXT 40
#define NBV  128
#define NSM  148

typedef unsigned int u32;
typedef unsigned long long u64;

// ---------------- scratch (static device globals; no allocation) -------------
__device__ int g_order[MAXT * 128];      // padded grouped order (-1 = pad)
__device__ int g_tile_cat[MAXT];
__device__ int g_tile_row[MAXT];         // padded row base, multiple of 128
__device__ int g_num_tiles;

// chunk-tiled, swizzled fp16 operands. A-tile = 128 rows x 64 halves (16KB).
// B-tile = 256 rows x 64 halves (32KB). Swizzle: halves idx = col ^ ((row&7)<<3).
__device__ __align__(16) __half g_at[MAXT * 8192];          // actions (1 chunk)
__device__ __align__(16) __half g_taut[16 * 8192];          // tau rows (16 chunks)
__device__ __align__(16) __half g_x1t[MAXT * 16 * 8192];    // a_emb (16 chunks)
__device__ __align__(16) __half g_h2t[MAXT * 16 * 8192];    // hidden (16 chunks)
__device__ __align__(16) __half g_W1t[NCAT * 4 * 16384];    // [cat][n0t] 1 chunk
__device__ __align__(16) __half g_W2A[NCAT * 64 * 16384];   // [cat][n0t][kc] k<1024
__device__ __align__(16) __half g_W2B[NCAT * 64 * 16384];   // k>=1024 (tau part)
__device__ __align__(16) __half g_W3t[NCAT * 64 * 16384];
__device__ __align__(16) float  g_tau[NCAT * NBV * HID];    // T[cat][t][n] fp32

// ---------------- helpers -----------------------------------------------------
__device__ __forceinline__ u32 smem_u32(const void* p) {
    u32 a;
    asm("{ .reg .u64 t; cvta.to.shared.u64 t, %1; cvt.u32.u64 %0, t; }"
        : "=r"(a) : "l"(p));
    return a;
}
__device__ __forceinline__ u32 hpack(__half a, __half b) {
    return ((u32)__half_as_ushort(b) << 16) | (u32)__half_as_ushort(a);
}
__device__ __forceinline__ u32 swz128(u32 o) { return o ^ ((o >> 3) & 0x70); }

__device__ __forceinline__ void mbar_init(u32 addr, u32 cnt) {
    asm volatile("mbarrier.init.shared.b64 [%0], %1;" :: "r"(addr), "r"(cnt) : "memory");
}
__device__ __forceinline__ void mbar_expect(u32 addr, u32 tx) {
    asm volatile("mbarrier.arrive.expect_tx.shared.b64 _, [%0], %1;"
                 :: "r"(addr), "r"(tx) : "memory");
}
__device__ __forceinline__ void mbar_wait(u32 addr, u32 phase) {
    asm volatile(
        "{\n\t.reg .pred P;\n\t"
        "W_%=:\n\t"
        "mbarrier.try_wait.parity.acquire.cta.shared::cta.b64 P, [%0], %1, 0x989680;\n\t"
        "@!P bra W_%=;\n\t}"
        :: "r"(addr), "r"(phase) : "memory");
}
__device__ __forceinline__ void bulkcp(u32 dst, const void* src, u32 bytes, u32 mbar) {
    asm volatile(
        "cp.async.bulk.shared::cluster.global.mbarrier::complete_tx::bytes "
        "[%0], [%1], %2, [%3];"
        :: "r"(dst), "l"(src), "r"(bytes), "r"(mbar) : "memory");
}
#define LDSM4(r, addr)                                                         \
    asm volatile("ldmatrix.sync.aligned.m8n8.x4.shared.b16 {%0,%1,%2,%3}, [%4];" \
                 : "=r"((r)[0]), "=r"((r)[1]), "=r"((r)[2]), "=r"((r)[3])      \
                 : "r"(addr))
#define MMA(d, a, b)                                                           \
    asm volatile("mma.sync.aligned.m16n8k16.row.col.f32.f16.f16.f32 "          \
                 "{%0,%1,%2,%3},{%4,%5,%6,%7},{%8,%9},{%0,%1,%2,%3};"          \
                 : "+f"((d)[0]), "+f"((d)[1]), "+f"((d)[2]), "+f"((d)[3])      \
                 : "r"((a)[0]), "r"((a)[1]), "r"((a)[2]), "r"((a)[3]),         \
                   "r"((b)[0]), "r"((b)[1]))

// ---------------- prep: padded ordering + tile table (one block) --------------
__global__ __launch_bounds__(256)
void k_prep(const int* __restrict__ cat_ids)
{
    __shared__ int thr_cnt[256 * NCAT];
    __shared__ int pb_s[NCAT];
    int tid = threadIdx.x;

    for (int i = tid; i < MAXT * 128; i += 256) g_order[i] = -1;

    int loc[NCAT];
    #pragma unroll
    for (int c = 0; c < NCAT; c++) loc[c] = 0;
    int i0 = tid * 16;
    #pragma unroll
    for (int j = 0; j < 16; j++) loc[cat_ids[i0 + j]]++;
    #pragma unroll
    for (int c = 0; c < NCAT; c++) thr_cnt[tid * NCAT + c] = loc[c];
    __syncthreads();
    if (tid < NCAT) {
        int run = 0;
        for (int i = 0; i < 256; i++) {
            int v = thr_cnt[i * NCAT + tid];
            thr_cnt[i * NCAT + tid] = run;
            run += v;
        }
        loc[0] = run;                      // total for this cat
        // store totals via shared
        pb_s[tid] = run;
    }
    __syncthreads();
    if (tid == 0) {
        int acc = 0, nt = 0;
        int pb[NCAT];
        for (int c = 0; c < NCAT; c++) {
            pb[c] = acc;
            int tot = pb_s[c];
            int ptiles = (tot + 127) >> 7;
            for (int r = 0; r < ptiles; r++) {
                g_tile_cat[nt] = c;
                g_tile_row[nt] = acc + r * 128;
                nt++;
            }
            acc += ptiles * 128;
        }
        g_num_tiles = nt;
        for (int c = 0; c < NCAT; c++) pb_s[c] = pb[c];
    }
    __syncthreads();
    int off[NCAT];
    #pragma unroll
    for (int c = 0; c < NCAT; c++)
        off[c] = pb_s[c] + thr_cnt[tid * NCAT + c];
    #pragma unroll
    for (int j = 0; j < 16; j++) {
        int cc = cat_ids[i0 + j];
        g_order[off[cc]++] = i0 + j;
    }
}

// ------- weight convert to tiled/swizzled fp16 + activation/tau regroup -------
__global__ __launch_bounds__(256)
void k_wsreg(const float* __restrict__ W1, const float* __restrict__ W2,
             const float* __restrict__ W3, const float* __restrict__ actions,
             const int* __restrict__ ts, int nb)
{
    int ky = blockIdx.y;
    int tid = threadIdx.x;

    if (ky == 98) {   // regroup: g_at fill + g_taut fill
        int id = (blockIdx.z * 32 + blockIdx.x) * 256 + tid;
        if (id < MAXT * 128 * 8) {
            int p = id >> 3, u8 = id & 7;
            int tok = g_order[p];
            __half h[8];
            if (tok >= 0) {
                const float* s = actions + (size_t)tok * ADIM + u8 * 8;
                float4 v0 = *(const float4*)s;
                float4 v1 = *(const float4*)(s + 4);
                h[0] = __float2half_rn(v0.x); h[1] = __float2half_rn(v0.y);
                h[2] = __float2half_rn(v0.z); h[3] = __float2half_rn(v0.w);
                h[4] = __float2half_rn(v1.x); h[5] = __float2half_rn(v1.y);
                h[6] = __float2half_rn(v1.z); h[7] = __float2half_rn(v1.w);
            } else {
                #pragma unroll
                for (int q = 0; q < 8; q++) h[q] = __ushort_as_half((unsigned short)0);
            }
            u32 hoff = (u32)(p >> 7) * 8192 + (p & 127) * 64 + ((u8 * 8) ^ ((p & 7) << 3));
            *(uint4*)(g_at + hoff) = *(uint4*)h;
        } else if (id < MAXT * 128 * 8 + 16384) {
            int id2 = id - MAXT * 128 * 8;
            int kc = id2 >> 10, rem = id2 & 1023;
            int t = rem >> 3, u8 = rem & 7;
            __half h[8];
            if (t < nb) {
                float tv = (float)ts[t];
                const float kcst = -9.210340371976184f / 512.0f;
                #pragma unroll
                for (int q = 0; q < 8; q++) {
                    int j = kc * 64 + u8 * 8 + q;
                    int m = j >> 1;
                    float ang = tv * expf((float)m * kcst);
                    float v = (j & 1) ? cosf(ang) : sinf(ang);
                    h[q] = __float2half_rn(v);
                }
            } else {
                #pragma unroll
                for (int q = 0; q < 8; q++) h[q] = __ushort_as_half((unsigned short)0);
            }
            u32 hoff = (u32)kc * 8192 + t * 64 + ((u8 * 8) ^ ((t & 7) << 3));
            *(uint4*)(g_taut + hoff) = *(uint4*)h;
        }
        return;
    }

    __shared__ float s[32][33];
    const float* src; int K, kt, layer;
    if (ky < 2)       { src = W1; K = ADIM;    kt = ky;      layer = 1; }
    else if (ky < 66) { src = W2; K = 2 * HID; kt = ky - 2;  layer = 2; }
    else              { src = W3; K = HID;     kt = ky - 66; layer = 3; }
    int n0b = blockIdx.x * 32, k0 = kt * 32, c = blockIdx.z;

    int kr = tid >> 3, n4 = (tid & 7) * 4;
    const float* sp = src + ((size_t)c * K + k0 + kr) * HID + n0b + n4;
    float4 v = *(const float4*)sp;
    s[kr][n4 + 0] = v.x; s[kr][n4 + 1] = v.y;
    s[kr][n4 + 2] = v.z; s[kr][n4 + 3] = v.w;
    __syncthreads();

    int nr = tid >> 3, k4 = (tid & 7) * 4;
    int n = n0b + nr;
    int kk = k0 + k4;
    u32 p0 = hpack(__float2half_rn(s[k4 + 0][nr]), __float2half_rn(s[k4 + 1][nr]));
    u32 p1 = hpack(__float2half_rn(s[k4 + 2][nr]), __float2half_rn(s[k4 + 3][nr]));

    __half* dst;
    u32 tile, hoff;
    if (layer == 1) {
        tile = c * 4 + (n >> 8);
        hoff = (u32)tile * 16384 + (n & 255) * 64 + ((kk & 63) ^ ((n & 7) << 3));
        dst = g_W1t;
    } else if (layer == 2) {
        int kk2 = kk & 1023;
        tile = (u32)(c * 4 + (n >> 8)) * 16 + (kk2 >> 6);
        hoff = tile * 16384 + (n & 255) * 64 + ((kk2 & 63) ^ ((n & 7) << 3));
        dst = (kk < 1024) ? g_W2A : g_W2B;
    } else {
        tile = (u32)(c * 4 + (n >> 8)) * 16 + (kk >> 6);
        hoff = tile * 16384 + (n & 255) * 64 + ((kk & 63) ^ ((n & 7) << 3));
        dst = g_W3t;
    }
    *(uint2*)(dst + hoff) = make_uint2(p0, p1);
}

// ---------------- persistent grouped HMMA GEMM (bulk-copy pipeline) -----------
// CTA 128x256, 8 warps (2x4), warp tile 64x64. K chunks of 64; 4-stage
// mbarrier pipeline fed by cp.async.bulk (1 thread, 2 bulks per stage).
#define A_OFF 0
#define B_OFF 16384
#define STG   49152
#define NSTG  4
#define SMEM_TOTAL (1024 + NSTG * STG)

template<int MODE>
__global__ __launch_bounds__(256, 1)
void k_pgemm(const float* __restrict__ b1, const float* __restrict__ b2,
             const float* __restrict__ b3, float* __restrict__ out_ext, int nb)
{
    extern __shared__ char smem[];
    int tid = threadIdx.x, lid = tid & 31, wid = tid >> 5;
    int wm = wid >> 2, wn = wid & 3;
    int* tok_s = (int*)smem;
    u32 sb   = smem_u32(smem);
    u32 sbar = sb + 640;
    u32 st0  = sb + 1024;

    if (tid == 0) {
        #pragma unroll
        for (int s4 = 0; s4 < NSTG; s4++) mbar_init(sbar + s4 * 8, 1);
    }

    u32 aRow[4], bRow[4];
    #pragma unroll
    for (int mt = 0; mt < 4; mt++)
        aRow[mt] = (wm * 64 + mt * 16 + (lid & 15)) * 128;
    u32 aHs = (lid >> 4) * 16;
    #pragma unroll
    for (int nh = 0; nh < 4; nh++)
        bRow[nh] = (wn * 64 + nh * 16 + (lid & 7) + ((lid >> 4) << 3)) * 128;
    u32 bHs = ((lid >> 3) & 1) * 16;

    __syncthreads();

    int nt = g_num_tiles;
    int nu = (MODE == 0) ? 32 + nt * 4 : nt * 4;
    int cc = 0;   // global chunk counter: stage = cc&3, parity = (cc>>2)&1

    for (int u = blockIdx.x; u < nu; u += gridDim.x) {
        __syncthreads();   // prior unit fully retired (epilogue, stages, tok_s)

        int cat, n0, nch, row0 = 0;
        bool tauu = false;
        const __half *a_base, *b_base;
        if (MODE == 0 && u < 32) {
            tauu = true;
            cat = u >> 2; n0 = (u & 3) * 256; nch = 16;
            a_base = g_taut;
            b_base = g_W2B + (size_t)(cat * 4 + (u & 3)) * 16 * 16384;
        } else if (MODE == 0) {
            int v = u - 32, tile = v >> 2;
            cat = g_tile_cat[tile]; row0 = g_tile_row[tile];
            n0 = (v & 3) * 256; nch = 1;
            a_base = g_at + (size_t)(row0 >> 7) * 8192;
            b_base = g_W1t + (size_t)(cat * 4 + (v & 3)) * 16384;
        } else if (MODE == 2) {
            int tile = u >> 2;
            cat = g_tile_cat[tile]; row0 = g_tile_row[tile];
            n0 = (u & 3) * 256; nch = 16;
            a_base = g_x1t + (size_t)(row0 >> 7) * 16 * 8192;
            b_base = g_W2A + (size_t)(cat * 4 + (u & 3)) * 16 * 16384;
        } else {
            int tile = u >> 2;
            cat = g_tile_cat[tile]; row0 = g_tile_row[tile];
            n0 = (u & 3) * 256; nch = 16;
            a_base = g_h2t + (size_t)(row0 >> 7) * 16 * 8192;
            b_base = g_W3t + (size_t)(cat * 4 + (u & 3)) * 16 * 16384;
        }

        if (tid < 128)
            tok_s[tid] = tauu ? ((tid < nb) ? tid : -1) : g_order[row0 + tid];

        if (tid == 0) {
            int pre = (nch < 3) ? nch : 3;
            for (int i = 0; i < pre; i++) {
                u32 s4 = (cc + i) & 3;
                u32 bar = sbar + s4 * 8;
                mbar_expect(bar, 49152);
                bulkcp(st0 + s4 * STG + A_OFF, a_base + i * 8192,  16384, bar);
                bulkcp(st0 + s4 * STG + B_OFF, b_base + i * 16384, 32768, bar);
            }
        }

        float acc[4][8][4];
        #pragma unroll
        for (int i = 0; i < 4; i++)
            #pragma unroll
            for (int j = 0; j < 8; j++)
                #pragma unroll
                for (int q = 0; q < 4; q++) acc[i][j][q] = 0.f;

        for (int c = 0; c < nch; c++) {
            mbar_wait(sbar + (cc & 3) * 8, (cc >> 2) & 1);
            u32 so = st0 + (cc & 3) * STG;
            #pragma unroll
            for (int s = 0; s < 4; s++) {
                u32 ah[4][4], bh[4][4];
                #pragma unroll
                for (int mt = 0; mt < 4; mt++)
                    LDSM4(ah[mt], so + A_OFF + swz128(aRow[mt] + s * 32 + aHs));
                #pragma unroll
                for (int nh = 0; nh < 4; nh++)
                    LDSM4(bh[nh], so + B_OFF + swz128(bRow[nh] + s * 32 + bHs));
                #pragma unroll
                for (int mt = 0; mt < 4; mt++)
                    #pragma unroll
                    for (int nh = 0; nh < 4; nh++) {
                        MMA(acc[mt][nh * 2 + 0], ah[mt], bh[nh] + 0);
                        MMA(acc[mt][nh * 2 + 1], ah[mt], bh[nh] + 2);
                    }
            }
            __syncthreads();
            if (tid == 0 && c + 3 < nch) {
                u32 s4 = (cc + 3) & 3;
                u32 bar = sbar + s4 * 8;
                mbar_expect(bar, 49152);
                bulkcp(st0 + s4 * STG + A_OFF, a_base + (c + 3) * 8192,  16384, bar);
                bulkcp(st0 + s4 * STG + B_OFF, b_base + (size_t)(c + 3) * 16384, 32768, bar);
            }
            cc++;
        }

        // ---- epilogue ----
        int g4 = lid >> 2, t4 = lid & 3;
        const float* bias = (MODE == 0) ? (tauu ? (const float*)0 : b1)
                          : (MODE == 2) ? b2 : b3;
        int tb = (row0 >> 7) * 16 + (n0 >> 6);   // act-store tile base (non-TAU)

        #pragma unroll
        for (int mt = 0; mt < 4; mt++) {
            int r0 = wm * 64 + mt * 16 + g4;
            int r1 = r0 + 8;
            int tok0 = tok_s[r0], tok1 = tok_s[r1];
            const float* T0 = 0;
            const float* T1 = 0;
            if (MODE == 2) {
                if (tok0 >= 0)
                    T0 = g_tau + ((size_t)cat * NBV + (tok0 % nb)) * HID + n0;
                if (tok1 >= 0)
                    T1 = g_tau + ((size_t)cat * NBV + (tok1 % nb)) * HID + n0;
            }
            #pragma unroll
            for (int j = 0; j < 8; j++) {
                int colh = j * 8 + t4 * 2;
                int col = wn * 64 + colh;
                float bb0 = bias ? bias[cat * HID + n0 + col] : 0.f;
                float bb1 = bias ? bias[cat * HID + n0 + col + 1] : 0.f;
                float v0 = acc[mt][j][0] + bb0;
                float v1 = acc[mt][j][1] + bb1;
                float v2 = acc[mt][j][2] + bb0;
                float v3 = acc[mt][j][3] + bb1;
                if (MODE == 2) {
                    if (T0) { v0 += T0[col]; v1 += T0[col + 1]; }
                    if (T1) { v2 += T1[col]; v3 += T1[col + 1]; }
                    v0 = v0 / (1.f + expf(-v0));
                    v1 = v1 / (1.f + expf(-v1));
                    v2 = v2 / (1.f + expf(-v2));
                    v3 = v3 / (1.f + expf(-v3));
                }
                if (MODE == 0 && tauu) {
                    if (tok0 >= 0)
                        *(float2*)(g_tau + ((size_t)cat * NBV + tok0) * HID + n0 + col)
                            = make_float2(v0, v1);
                    if (tok1 >= 0)
                        *(float2*)(g_tau + ((size_t)cat * NBV + tok1) * HID + n0 + col)
                            = make_float2(v2, v3);
                } else if (MODE == 3) {
                    if (tok0 >= 0)
                        *(float2*)(out_ext + (size_t)tok0 * HID + n0 + col)
                            = make_float2(v0, v1);
                    if (tok1 >= 0)
                        *(float2*)(out_ext + (size_t)tok1 * HID + n0 + col)
                            = make_float2(v2, v3);
                } else {
                    __half* dst = (MODE == 0) ? g_x1t : g_h2t;
                    u32 o0 = (u32)(tb + wn) * 8192 + r0 * 64 + (colh ^ ((r0 & 7) << 3));
                    u32 o1 = (u32)(tb + wn) * 8192 + r1 * 64 + (colh ^ ((r1 & 7) << 3));
                    *(u32*)(dst + o0) = hpack(__float2half_rn(v0), __float2half_rn(v1));
                    *(u32*)(dst + o1) = hpack(__float2half_rn(v2), __float2half_rn(v3));
                }
            }
        }
    }
}

// ------------------------------ launch ---------------------------------------
extern "C" void kernel_launch(void* const* d_in, const int* in_sizes, int n_in,
                              void* d_out, int out_size)
{
    const float* actions   = (const float*)d_in[0];
    const int*   timesteps = (const int*)d_in[1];
    const int*   cat_ids   = (const int*)d_in[2];
    const float* W1 = (const float*)d_in[3];
    const float* b1 = (const float*)d_in[4];
    const float* W2 = (const float*)d_in[5];
    const float* b2 = (const float*)d_in[6];
    const float* W3 = (const float*)d_in[7];
    const float* b3 = (const float*)d_in[8];
    float* out = (float*)d_out;
    int nb = in_sizes[1];
    if (nb > NBV) nb = NBV;   // dataset: nb = 128

    cudaFuncSetAttribute((const void*)k_pgemm<0>,
                         cudaFuncAttributeMaxDynamicSharedMemorySize, SMEM_TOTAL);
    cudaFuncSetAttribute((const void*)k_pgemm<2>,
                         cudaFuncAttributeMaxDynamicSharedMemorySize, SMEM_TOTAL);
    cudaFuncSetAttribute((const void*)k_pgemm<3>,
                         cudaFuncAttributeMaxDynamicSharedMemorySize, SMEM_TOTAL);

    // 0: padded ordering + tile table
    k_prep<<<1, 256>>>(cat_ids);
    // 1: weight convert to tiled layout + action/tau regroup (ky==98)
    k_wsreg<<<dim3(32, 99, 8), 256>>>(W1, W2, W3, actions, timesteps, nb);
    // 2: TAU table + L1 (persistent)
    k_pgemm<0><<<NSM, 256, SMEM_TOTAL>>>(b1, b2, b3, out, nb);
    // 3 (ncu-captured): L2 with tau-add + SiLU
    k_pgemm<2><<<NSM, 256, SMEM_TOTAL>>>(b1, b2, b3, out, nb);
    // 4: L3 -> fp32 out
    k_pgemm<3><<<NSM, 256, SMEM_TOTAL>>>(b1, b2, b3, out, nb);
}

// round 10
// speedup vs baseline: 1.1403x; 1.1403x over previous
#include <cuda_runtime.h>
#include <cuda_fp16.h>
#include <math.h>

#define NTOK 4096
#define HID  1024
#define ADIM 64
#define NCAT 8
#define MAXT 40
#define NBV  128

typedef unsigned int u32;
typedef unsigned long long u64;

// ---------------- scratch (static device globals; no allocation) -------------
__device__ int g_order[NTOK];
__device__ int g_tile_cat[MAXT];
__device__ int g_tile_row[MAXT];
__device__ int g_cat_base[NCAT];
__device__ int g_cat_count[NCAT];
__device__ int g_num_tiles;

__device__ __align__(16) __half g_ah[NTOK * ADIM];      // actions fp16
__device__ __align__(16) __half g_tauh[NBV * HID];      // tau_emb fp16 (128 rows)
__device__ __align__(16) __half g_x1h[NTOK * HID];      // a_emb fp16
__device__ __align__(16) __half g_h2h[NTOK * HID];      // hidden fp16
__device__ __align__(16) float  g_tau[NCAT * NBV * HID];// T[cat][t][n] fp32

// converted weights: [c][n][k] fp16 (k contiguous, full K rows)
#define W1OFF 0
#define W1SZ  (NCAT * HID * ADIM)
#define W2OFF (W1OFF + W1SZ)
#define W2SZ  (NCAT * HID * 2 * HID)
#define W3OFF (W2OFF + W2SZ)
#define W3SZ  (NCAT * HID * HID)
#define WTOT  (W3OFF + W3SZ)
__device__ __align__(16) __half g_Wh[WTOT];

// ---------------- helpers -----------------------------------------------------
__device__ __forceinline__ u32 smem_u32(const void* p) {
    u32 a;
    asm("{ .reg .u64 t; cvta.to.shared.u64 t, %1; cvt.u32.u64 %0, t; }"
        : "=r"(a) : "l"(p));
    return a;
}
__device__ __forceinline__ u32 hpack(__half a, __half b) {
    return ((u32)__half_as_ushort(b) << 16) | (u32)__half_as_ushort(a);
}
__device__ __forceinline__ u32 swz128(u32 o) { return o ^ ((o >> 3) & 0x70); }

__device__ __forceinline__ void cpasync16(u32 dst, const void* src, u32 srcsz) {
    asm volatile("cp.async.cg.shared.global [%0], [%1], 16, %2;"
                 :: "r"(dst), "l"(src), "r"(srcsz) : "memory");
}
__device__ __forceinline__ void cp_commit() {
    asm volatile("cp.async.commit_group;" ::: "memory");
}
__device__ __forceinline__ void cp_wait2() {
    asm volatile("cp.async.wait_group 2;" ::: "memory");
}
#define LDSM4(r, addr)                                                         \
    asm volatile("ldmatrix.sync.aligned.m8n8.x4.shared.b16 {%0,%1,%2,%3}, [%4];" \
                 : "=r"((r)[0]), "=r"((r)[1]), "=r"((r)[2]), "=r"((r)[3])      \
                 : "r"(addr))
#define MMA(d, a, b)                                                           \
    asm volatile("mma.sync.aligned.m16n8k16.row.col.f32.f16.f16.f32 "          \
                 "{%0,%1,%2,%3},{%4,%5,%6,%7},{%8,%9},{%0,%1,%2,%3};"          \
                 : "+f"((d)[0]), "+f"((d)[1]), "+f"((d)[2]), "+f"((d)[3])      \
                 : "r"((a)[0]), "r"((a)[1]), "r"((a)[2]), "r"((a)[3]),         \
                   "r"((b)[0]), "r"((b)[1]))

// ---------------- prep: ordering (block 0) + tauh + act cvt + tau zero --------
__global__ __launch_bounds__(256)
void k_prep(const int* __restrict__ cat_ids, const int* __restrict__ ts,
            const float* __restrict__ actions, int nb)
{
    int tid = threadIdx.x;
    if (blockIdx.x == 0) {
        __shared__ int thr_cnt[256 * NCAT];
        __shared__ int cat_tot[NCAT];
        __shared__ int cat_base_s[NCAT];
        int loc[NCAT];
        #pragma unroll
        for (int c = 0; c < NCAT; c++) loc[c] = 0;
        int i0 = tid * 16;
        #pragma unroll
        for (int j = 0; j < 16; j++) loc[cat_ids[i0 + j]]++;
        #pragma unroll
        for (int c = 0; c < NCAT; c++) thr_cnt[tid * NCAT + c] = loc[c];
        __syncthreads();
        if (tid < NCAT) {
            int run = 0;
            for (int i = 0; i < 256; i++) {
                int v = thr_cnt[i * NCAT + tid];
                thr_cnt[i * NCAT + tid] = run;
                run += v;
            }
            cat_tot[tid] = run;
        }
        __syncthreads();
        if (tid == 0) {
            int acc = 0, nt = 0;
            for (int c = 0; c < NCAT; c++) {
                g_cat_base[c]  = acc;
                g_cat_count[c] = cat_tot[c];
                cat_base_s[c]  = acc;
                for (int r = 0; r < cat_tot[c]; r += 128) {
                    g_tile_cat[nt] = c;
                    g_tile_row[nt] = acc + r;
                    nt++;
                }
                acc += cat_tot[c];
            }
            g_num_tiles = nt;
        }
        __syncthreads();
        int off[NCAT];
        #pragma unroll
        for (int c = 0; c < NCAT; c++)
            off[c] = cat_base_s[c] + thr_cnt[tid * NCAT + c];
        #pragma unroll
        for (int j = 0; j < 16; j++) {
            int cc = cat_ids[i0 + j];
            g_order[off[cc]++] = i0 + j;
        }
        return;
    }
    int gt = (blockIdx.x - 1) * 256 + tid;
    int stride = (gridDim.x - 1) * 256;
    const float kc = -9.210340371976184f / 512.0f;
    // tau_emb rows (zero beyond nb)
    for (int idx = gt; idx < NBV * HID; idx += stride) {
        int t = idx >> 10;
        int j = idx & (HID - 1);
        float v = 0.f;
        if (t < nb) {
            int m = j >> 1;
            float tv = (float)ts[t];
            float ang = tv * expf((float)m * kc);
            v = (j & 1) ? cosf(ang) : sinf(ang);
        }
        g_tauh[idx] = __float2half_rn(v);
    }
    // actions fp16
    for (int idx = gt; idx < NTOK * ADIM; idx += stride)
        g_ah[idx] = __float2half_rn(actions[idx]);
    // zero T table (accumulated by atomicAdd)
    for (int idx = gt; idx < NCAT * NBV * HID / 4; idx += stride)
        ((float4*)g_tau)[idx] = make_float4(0.f, 0.f, 0.f, 0.f);
}

// ------- weight convert + transpose, coalesced 128B stores --------------------
// tile: 32 n x 64 k. Read coalesced float4; smem transpose; write one uint4
// (8 halves) per thread -> 8 threads form a full 128B line along k.
__global__ __launch_bounds__(256)
void k_wsplit(const float* __restrict__ W1, const float* __restrict__ W2,
              const float* __restrict__ W3)
{
    __shared__ float s[32][72];
    int ky = blockIdx.y;
    const float* src; size_t woff; int K, kt;
    if (ky < 1)       { src = W1; woff = W1OFF; K = ADIM;    kt = ky; }
    else if (ky < 33) { src = W2; woff = W2OFF; K = 2 * HID; kt = ky - 1; }
    else              { src = W3; woff = W3OFF; K = HID;     kt = ky - 33; }
    int n0 = blockIdx.x * 32, k0 = kt * 64, c = blockIdx.z;
    int tid = threadIdx.x;

    #pragma unroll
    for (int i = 0; i < 2; i++) {
        int idx = tid + i * 256;
        int kr = idx >> 3, n4 = (idx & 7) * 4;
        float4 v = *(const float4*)(src + ((size_t)c * K + k0 + kr) * HID + n0 + n4);
        s[n4 + 0][kr] = v.x;
        s[n4 + 1][kr] = v.y;
        s[n4 + 2][kr] = v.z;
        s[n4 + 3][kr] = v.w;
    }
    __syncthreads();

    int nr = tid >> 3, k8 = (tid & 7) * 8;
    u32 p[4];
    #pragma unroll
    for (int q = 0; q < 4; q++)
        p[q] = hpack(__float2half_rn(s[nr][k8 + 2 * q]),
                     __float2half_rn(s[nr][k8 + 2 * q + 1]));
    size_t di = woff + ((size_t)c * HID + n0 + nr) * (size_t)K + k0 + k8;
    *(uint4*)(g_Wh + di) = make_uint4(p[0], p[1], p[2], p[3]);
}

// ---------------- grouped HMMA GEMM (R5 structure, one unit per CTA) ----------
// CTA 128x256, 8 warps (2x4), warp tile 64x64. K chunks of 64, 4-stage
// cp.async pipeline (wait_group 2). SW128 smem rows of 128B.
// MODE 0: 1D grid; bid<64 -> TAU K-split units (atomicAdd -> g_tau);
//         else L1 units (-> g_x1h). MODE 2: L2 (+T +b2 +SiLU -> g_h2h).
// MODE 3: L3 (-> fp32 out).
#define A_OFF 0
#define B_OFF 16384
#define STG   49152
#define NSTG  4
#define SMEM_TOTAL (1024 + NSTG * STG)

template<int MODE>
__global__ __launch_bounds__(256, 1)
void k_gm(const float* __restrict__ bias_g, float* __restrict__ out_ext, int nb)
{
    extern __shared__ char smem[];
    int tid = threadIdx.x, lid = tid & 31, wid = tid >> 5;
    int wm = wid >> 2, wn = wid & 3;

    int cat, n0, nvalid, row0 = 0, K, ldin, ldw, koff;
    bool tauu = false;
    const __half* inp;
    size_t wb;
    if (MODE == 0) {
        int b = blockIdx.x;
        if (b < 64) {
            tauu = true;
            int ks = b & 1;
            n0 = ((b >> 1) & 3) * 256;
            cat = b >> 3;
            K = 512; ldin = HID; ldw = 2 * HID; koff = HID + ks * 512;
            inp = g_tauh + ks * 512;   // FIX: A reads matching K-slice of tau_emb
            wb = W2OFF;
            nvalid = 128;
        } else {
            int v = b - 64;
            int tile = v >> 2;
            if (tile >= g_num_tiles) return;
            cat = g_tile_cat[tile]; row0 = g_tile_row[tile];
            n0 = (v & 3) * 256;
            K = ADIM; ldin = ADIM; ldw = ADIM; koff = 0;
            inp = g_ah; wb = W1OFF;
            nvalid = g_cat_base[cat] + g_cat_count[cat] - row0;
            if (nvalid > 128) nvalid = 128;
        }
    } else {
        int tile = blockIdx.x;
        if (tile >= g_num_tiles) return;
        cat = g_tile_cat[tile]; row0 = g_tile_row[tile];
        n0 = blockIdx.y * 256;
        K = HID; ldin = HID; koff = 0;
        if (MODE == 2) { ldw = 2 * HID; inp = g_x1h; wb = W2OFF; }
        else           { ldw = HID;     inp = g_h2h; wb = W3OFF; }
        nvalid = g_cat_base[cat] + g_cat_count[cat] - row0;
        if (nvalid > 128) nvalid = 128;
    }

    int* tok_s = (int*)smem;
    if (tid < 128)
        tok_s[tid] = (tid < nvalid) ? (tauu ? tid : g_order[row0 + tid]) : -1;
    __syncthreads();

    u32 st0 = smem_u32(smem) + 1024;

    // ---- cp.async descriptors ----
    int am = tid >> 3, ac = tid & 7;
    const __half* a_src[4];
    u32 a_sz[4];
    u32 dst0 = swz128(am * 128 + ac * 16);
    #pragma unroll
    for (int i = 0; i < 4; i++) {
        int tok = tok_s[am + 32 * i];
        int t2 = (tok < 0) ? 0 : tok;
        a_src[i] = inp + (size_t)t2 * ldin + ac * 8;
        a_sz[i] = (tok < 0) ? 0u : 16u;
    }
    const __half* b_src0 = g_Wh + wb +
                           ((size_t)cat * HID + n0 + am) * (size_t)ldw + koff + ac * 8;
    size_t b_stride = (size_t)32 * ldw;

    // ---- ldmatrix row bases ----
    u32 aRow[4], bRow[4];
    #pragma unroll
    for (int mt = 0; mt < 4; mt++)
        aRow[mt] = (wm * 64 + mt * 16 + (lid & 15)) * 128;
    u32 aHs = (lid >> 4) * 16;
    #pragma unroll
    for (int nh = 0; nh < 4; nh++)
        bRow[nh] = (wn * 64 + nh * 16 + (lid & 7) + ((lid >> 4) << 3)) * 128;
    u32 bHs = ((lid >> 3) & 1) * 16;

    float acc[4][8][4];
    #pragma unroll
    for (int i = 0; i < 4; i++)
        #pragma unroll
        for (int j = 0; j < 8; j++)
            #pragma unroll
            for (int q = 0; q < 4; q++) acc[i][j][q] = 0.f;

    int nch = K / 64;

    auto issue = [&](int ch) {
        if (ch < nch) {
            int kg = ch * 64;
            u32 so = st0 + (ch & (NSTG - 1)) * STG;
            #pragma unroll
            for (int i = 0; i < 4; i++)
                cpasync16(so + A_OFF + dst0 + i * 4096, a_src[i] + kg, a_sz[i]);
            #pragma unroll
            for (int i = 0; i < 8; i++)
                cpasync16(so + B_OFF + dst0 + i * 4096, b_src0 + i * b_stride + kg, 16);
        }
        cp_commit();   // empty group when ch >= nch keeps wait_group uniform
    };

    issue(0); issue(1); issue(2);

    for (int c = 0; c < nch; c++) {
        cp_wait2();
        __syncthreads();
        issue(c + 3);

        u32 so = st0 + (c & (NSTG - 1)) * STG;
        #pragma unroll
        for (int s = 0; s < 4; s++) {
            u32 ah[4][4], bh[4][4];
            #pragma unroll
            for (int mt = 0; mt < 4; mt++)
                LDSM4(ah[mt], so + A_OFF + swz128(aRow[mt] + s * 32 + aHs));
            #pragma unroll
            for (int nh = 0; nh < 4; nh++)
                LDSM4(bh[nh], so + B_OFF + swz128(bRow[nh] + s * 32 + bHs));
            #pragma unroll
            for (int mt = 0; mt < 4; mt++)
                #pragma unroll
                for (int nh = 0; nh < 4; nh++) {
                    MMA(acc[mt][nh * 2 + 0], ah[mt], bh[nh] + 0);
                    MMA(acc[mt][nh * 2 + 1], ah[mt], bh[nh] + 2);
                }
        }
    }

    // ---- epilogue ----
    int g4 = lid >> 2, t4 = lid & 3;

    #pragma unroll
    for (int mt = 0; mt < 4; mt++) {
        int r0 = wm * 64 + mt * 16 + g4;
        int tok0 = tok_s[r0], tok1 = tok_s[r0 + 8];
        const float *T0 = 0, *T1 = 0;
        if (MODE == 2) {
            if (tok0 >= 0)
                T0 = g_tau + ((size_t)cat * NBV + (tok0 % nb)) * HID + n0;
            if (tok1 >= 0)
                T1 = g_tau + ((size_t)cat * NBV + (tok1 % nb)) * HID + n0;
        }
        #pragma unroll
        for (int j = 0; j < 8; j++) {
            int col = wn * 64 + j * 8 + t4 * 2;
            float bb0 = 0.f, bb1 = 0.f;
            if (!(MODE == 0 && tauu)) {
                bb0 = bias_g[cat * HID + n0 + col];
                bb1 = bias_g[cat * HID + n0 + col + 1];
            }
            float v0 = acc[mt][j][0] + bb0;
            float v1 = acc[mt][j][1] + bb1;
            float v2 = acc[mt][j][2] + bb0;
            float v3 = acc[mt][j][3] + bb1;
            if (MODE == 2) {
                if (T0) { v0 += T0[col]; v1 += T0[col + 1]; }
                if (T1) { v2 += T1[col]; v3 += T1[col + 1]; }
                v0 = v0 / (1.f + expf(-v0));
                v1 = v1 / (1.f + expf(-v1));
                v2 = v2 / (1.f + expf(-v2));
                v3 = v3 / (1.f + expf(-v3));
            }
            if (MODE == 0 && tauu) {
                float* tb = g_tau + (size_t)cat * NBV * HID + n0 + col;
                atomicAdd(tb + (size_t)tok0 * HID,     v0);
                atomicAdd(tb + (size_t)tok0 * HID + 1, v1);
                atomicAdd(tb + (size_t)tok1 * HID,     v2);
                atomicAdd(tb + (size_t)tok1 * HID + 1, v3);
            } else if (MODE == 3) {
                if (tok0 >= 0)
                    *(float2*)(out_ext + (size_t)tok0 * HID + n0 + col) = make_float2(v0, v1);
                if (tok1 >= 0)
                    *(float2*)(out_ext + (size_t)tok1 * HID + n0 + col) = make_float2(v2, v3);
            } else {
                __half* oh = (MODE == 0) ? g_x1h : g_h2h;
                if (tok0 >= 0)
                    *(u32*)(oh + (size_t)tok0 * HID + n0 + col) =
                        hpack(__float2half_rn(v0), __float2half_rn(v1));
                if (tok1 >= 0)
                    *(u32*)(oh + (size_t)tok1 * HID + n0 + col) =
                        hpack(__float2half_rn(v2), __float2half_rn(v3));
            }
        }
    }
}

// ------------------------------ launch ---------------------------------------
extern "C" void kernel_launch(void* const* d_in, const int* in_sizes, int n_in,
                              void* d_out, int out_size)
{
    const float* actions   = (const float*)d_in[0];
    const int*   timesteps = (const int*)d_in[1];
    const int*   cat_ids   = (const int*)d_in[2];
    const float* W1 = (const float*)d_in[3];
    const float* b1 = (const float*)d_in[4];
    const float* W2 = (const float*)d_in[5];
    const float* b2 = (const float*)d_in[6];
    const float* W3 = (const float*)d_in[7];
    const float* b3 = (const float*)d_in[8];
    float* out = (float*)d_out;
    int nb = in_sizes[1];
    if (nb > NBV) nb = NBV;   // dataset: nb = 128

    cudaFuncSetAttribute((const void*)k_gm<0>,
                         cudaFuncAttributeMaxDynamicSharedMemorySize, SMEM_TOTAL);
    cudaFuncSetAttribute((const void*)k_gm<2>,
                         cudaFuncAttributeMaxDynamicSharedMemorySize, SMEM_TOTAL);
    cudaFuncSetAttribute((const void*)k_gm<3>,
                         cudaFuncAttributeMaxDynamicSharedMemorySize, SMEM_TOTAL);

    // 0: prep (ordering + tauh rows + action convert + T zero)
    k_prep<<<129, 256>>>(cat_ids, timesteps, actions, nb);
    // 1: weight convert+transpose, coalesced
    k_wsplit<<<dim3(32, 49, 8), 256>>>(W1, W2, W3);
    // 2: TAU (K-split x2, 64 CTAs) + L1 (160 CTAs), fused
    k_gm<0><<<224, 256, SMEM_TOTAL>>>(b1, out, nb);
    // 3 (ncu-captured): L2 with T-add + SiLU
    k_gm<2><<<dim3(MAXT, 4), 256, SMEM_TOTAL>>>(b2, out, nb);
    // 4: L3 -> fp32 out
    k_gm<3><<<dim3(MAXT, 4), 256, SMEM_TOTAL>>>(b3, out, nb);
}